// round 2
// baseline (speedup 1.0000x reference)
#include <cuda_runtime.h>
#include <cuda_bf16.h>
#include <cfloat>
#include <math.h>

#define HID   1024
#define HEADC 16002
#define C0LO  16000
#define C0HI  28000
#define P0    256
#define P1    64
#define T0C   12000
#define T1C   8000
#define MAXTOK 4096

// ---------------- scratch (no allocations allowed) ----------------
__device__ float g_proj0[MAXTOK * P0];
__device__ float g_proj1[MAXTOK * P1];
__device__ int   g_idx0[MAXTOK];
__device__ int   g_idx1[MAXTOK];
__device__ int   g_cnt[2];
__device__ float g_pm[2][MAXTOK];
__device__ float g_ps[2][MAXTOK];
__device__ float g_plab[2][MAXTOK];
__device__ float g_lt0[MAXTOK];
__device__ float g_lt1[MAXTOK];

// ---------------- gather tokens per cluster ----------------
__global__ void gather_kernel(const int* __restrict__ labels, int ntok)
{
    __shared__ int c0, c1;
    if (threadIdx.x == 0) { c0 = 0; c1 = 0; }
    __syncthreads();
    for (int i = threadIdx.x; i < ntok; i += blockDim.x) {
        int l = labels[i];
        if (l >= C0LO) {
            if (l < C0HI) g_idx0[atomicAdd(&c0, 1)] = i;
            else          g_idx1[atomicAdd(&c1, 1)] = i;
        }
    }
    __syncthreads();
    if (threadIdx.x == 0) { g_cnt[0] = c0; g_cnt[1] = c1; }
}

// ---------------- projections (only for gathered tokens) ----------------
__global__ void proj0_kernel(const float* __restrict__ inp,
                             const float* __restrict__ pW,
                             const float* __restrict__ pb)
{
    __shared__ float As[8][HID];   // 32 KB
    int n = g_cnt[0];
    int g0 = blockIdx.x * 8;
    if (g0 >= n) return;
    int tid = threadIdx.x;
    for (int e = tid; e < 8 * HID; e += 256) {
        int r = e >> 10, k = e & 1023;
        int g = g0 + r;
        As[r][k] = (g < n) ? inp[(size_t)g_idx0[g] * HID + k] : 0.f;
    }
    __syncthreads();
    float acc[8];
    #pragma unroll
    for (int t = 0; t < 8; t++) acc[t] = 0.f;
    float bj = pb[tid];
    #pragma unroll 4
    for (int k = 0; k < HID; k++) {
        float w = pW[k * P0 + tid];
        #pragma unroll
        for (int t = 0; t < 8; t++) acc[t] = fmaf(As[t][k], w, acc[t]);
    }
    #pragma unroll
    for (int t = 0; t < 8; t++) {
        int g = g0 + t;
        if (g < n) g_proj0[(size_t)g * P0 + tid] = acc[t] + bj;
    }
}

__global__ void proj1_kernel(const float* __restrict__ inp,
                             const float* __restrict__ pW,
                             const float* __restrict__ pb)
{
    __shared__ float As[8][HID];
    int n = g_cnt[1];
    int g0 = blockIdx.x * 8;
    if (g0 >= n) return;
    int tid = threadIdx.x;
    for (int e = tid; e < 8 * HID; e += 256) {
        int r = e >> 10, k = e & 1023;
        int g = g0 + r;
        As[r][k] = (g < n) ? inp[(size_t)g_idx1[g] * HID + k] : 0.f;
    }
    __syncthreads();
    int j  = tid & 63;
    int tg = tid >> 6;           // 0..3, two tokens each
    float acc0 = 0.f, acc1 = 0.f;
    float bj = pb[j];
    #pragma unroll 4
    for (int k = 0; k < HID; k++) {
        float w = pW[k * P1 + j];
        acc0 = fmaf(As[tg * 2 + 0][k], w, acc0);
        acc1 = fmaf(As[tg * 2 + 1][k], w, acc1);
    }
    int g = g0 + tg * 2;
    if (g < n)     g_proj1[(size_t)g * P1 + j]       = acc0 + bj;
    if (g + 1 < n) g_proj1[(size_t)(g + 1) * P1 + j] = acc1 + bj;
}

// ---------------- head: fused GEMM + online logsumexp (class-split x2) ----------------
__global__ void __launch_bounds__(256, 2)
head_kernel(const float* __restrict__ inp, const int* __restrict__ labels,
            const float* __restrict__ W, const float* __restrict__ bias)
{
    extern __shared__ unsigned char smem_raw[];
    __nv_bfloat16* As = reinterpret_cast<__nv_bfloat16*>(smem_raw);     // [32][1024] bf16 = 64KB
    float* Bs = reinterpret_cast<float*>(smem_raw + 32 * HID * 2);      // [32][256] f32 = 32KB
    __shared__ int hlab[32];

    const int tid  = threadIdx.x;
    const int tx   = tid & 31;
    const int ty   = tid >> 5;
    const int tok0 = blockIdx.x * 32;
    const int split = blockIdx.y;

    {   // load A tile (fp32 -> bf16), tokens contiguous so linear copy is fine
        const float4* in4 = reinterpret_cast<const float4*>(inp + (size_t)tok0 * HID);
        #pragma unroll 4
        for (int e = tid; e < 32 * HID / 4; e += 256) {
            float4 v = in4[e];
            int b = e * 4;
            As[b + 0] = __float2bfloat16(v.x);
            As[b + 1] = __float2bfloat16(v.y);
            As[b + 2] = __float2bfloat16(v.z);
            As[b + 3] = __float2bfloat16(v.w);
        }
    }
    if (tid < 32) {
        int l = labels[tok0 + tid];
        hlab[tid] = (l < C0LO) ? l : ((l < C0HI) ? C0LO : C0LO + 1);
    }
    __syncthreads();

    float m[4], s[4], lab[4];
    int myhl[4];
    #pragma unroll
    for (int j = 0; j < 4; j++) { m[j] = -FLT_MAX; s[j] = 0.f; lab[j] = -FLT_MAX; myhl[j] = hlab[j * 8 + ty]; }

    const int cstart = split * 8192;

    #pragma unroll 1
    for (int tile = 0; tile < 32; ++tile) {
        const int cbase = cstart + tile * 256;
        if (cbase >= HEADC) break;   // uniform across block

        float acc[4][8];
        #pragma unroll
        for (int j = 0; j < 4; j++)
            #pragma unroll
            for (int i = 0; i < 8; i++) acc[j][i] = 0.f;

        #pragma unroll 1
        for (int kt = 0; kt < HID; kt += 32) {
            __syncthreads();
            {
                int c = cbase + tid;
                bool v = c < HEADC;
                const float* Wp = W + (size_t)kt * HEADC + c;
                #pragma unroll
                for (int r = 0; r < 32; ++r)
                    Bs[r * 256 + tid] = v ? Wp[(size_t)r * HEADC] : 0.f;
            }
            __syncthreads();
            #pragma unroll
            for (int k = 0; k < 32; ++k) {
                float a[4];
                #pragma unroll
                for (int j = 0; j < 4; j++)
                    a[j] = __bfloat162float(As[(j * 8 + ty) * HID + kt + k]);
                const float* bp = Bs + k * 256 + tx * 8;
                float bb[8];
                #pragma unroll
                for (int i = 0; i < 8; i++) bb[i] = bp[i];
                #pragma unroll
                for (int j = 0; j < 4; j++)
                    #pragma unroll
                    for (int i = 0; i < 8; i++)
                        acc[j][i] = fmaf(a[j], bb[i], acc[j][i]);
            }
        }
        // epilogue: bias + validity + online logsumexp update + label logit
        #pragma unroll
        for (int i = 0; i < 8; i++) {
            int c = cbase + tx * 8 + i;
            bool v = c < HEADC;
            float bv = v ? bias[c] : 0.f;
            #pragma unroll
            for (int j = 0; j < 4; j++)
                acc[j][i] = v ? (acc[j][i] + bv) : -FLT_MAX;
        }
        #pragma unroll
        for (int j = 0; j < 4; j++) {
            float tm = acc[j][0];
            #pragma unroll
            for (int i = 1; i < 8; i++) tm = fmaxf(tm, acc[j][i]);
            float nm = fmaxf(m[j], tm);
            float es = 0.f;
            #pragma unroll
            for (int i = 0; i < 8; i++) es += __expf(acc[j][i] - nm);
            s[j] = s[j] * __expf(m[j] - nm) + es;
            m[j] = nm;
            int hl = myhl[j];
            #pragma unroll
            for (int i = 0; i < 8; i++) {
                int c = cbase + tx * 8 + i;
                if (c == hl) lab[j] = acc[j][i];
            }
        }
    }
    // warp reduce: lanes of one warp hold disjoint class ranges of same 4 tokens
    #pragma unroll
    for (int j = 0; j < 4; j++) {
        float mw = m[j];
        #pragma unroll
        for (int o = 16; o > 0; o >>= 1) mw = fmaxf(mw, __shfl_xor_sync(0xffffffffu, mw, o));
        float sl = s[j] * __expf(m[j] - mw);
        #pragma unroll
        for (int o = 16; o > 0; o >>= 1) sl += __shfl_xor_sync(0xffffffffu, sl, o);
        float lw = lab[j];
        #pragma unroll
        for (int o = 16; o > 0; o >>= 1) lw = fmaxf(lw, __shfl_xor_sync(0xffffffffu, lw, o));
        if (tx == 0) {
            int t = tok0 + j * 8 + ty;
            g_pm[split][t]   = mw;
            g_ps[split][t]   = sl;
            g_plab[split][t] = lw;
        }
    }
}

// ---------------- tails: fused GEMM + full CE on gathered tokens ----------------
template<int K, int C, int CL>
__global__ void __launch_bounds__(256, 2)
tail_kernel(const int* __restrict__ labels,
            const float* __restrict__ W, const float* __restrict__ bias, int lo)
{
    extern __shared__ unsigned char smem_raw[];
    float* As = reinterpret_cast<float*>(smem_raw);            // [32][K]
    float* Bs = reinterpret_cast<float*>(smem_raw) + 32 * K;   // [32][256]
    __shared__ int tlab[32];
    __shared__ int torig[32];

    const int* idx = (CL == 0) ? g_idx0 : g_idx1;
    const float* Aproj = (CL == 0) ? g_proj0 : g_proj1;
    float* lossout = (CL == 0) ? g_lt0 : g_lt1;

    int n  = g_cnt[CL];
    int g0 = blockIdx.x * 32;
    if (g0 >= n) return;

    const int tid = threadIdx.x;
    const int tx  = tid & 31;
    const int ty  = tid >> 5;

    for (int e = tid; e < 32 * K; e += 256) {
        int r = e / K, k = e % K;
        int g = g0 + r;
        As[r * K + k] = (g < n) ? Aproj[(size_t)idx[g] * K + k] : 0.f;
    }
    if (tid < 32) {
        int g = g0 + tid;
        if (g < n) { int o = idx[g]; torig[tid] = o; tlab[tid] = labels[o] - lo; }
        else       { torig[tid] = -1; tlab[tid] = -1; }
    }
    __syncthreads();

    constexpr int NT = (C + 255) / 256;
    float m[4], s[4], lab[4];
    int mytl[4];
    #pragma unroll
    for (int j = 0; j < 4; j++) { m[j] = -FLT_MAX; s[j] = 0.f; lab[j] = -FLT_MAX; mytl[j] = tlab[j * 8 + ty]; }

    #pragma unroll 1
    for (int tile = 0; tile < NT; ++tile) {
        const int cbase = tile * 256;
        float acc[4][8];
        #pragma unroll
        for (int j = 0; j < 4; j++)
            #pragma unroll
            for (int i = 0; i < 8; i++) acc[j][i] = 0.f;

        #pragma unroll 1
        for (int kt = 0; kt < K; kt += 32) {
            __syncthreads();
            {
                int c = cbase + tid;
                bool v = c < C;
                const float* Wp = W + (size_t)kt * C + c;
                #pragma unroll
                for (int r = 0; r < 32; ++r)
                    Bs[r * 256 + tid] = v ? Wp[(size_t)r * C] : 0.f;
            }
            __syncthreads();
            #pragma unroll
            for (int k = 0; k < 32; ++k) {
                float a[4];
                #pragma unroll
                for (int j = 0; j < 4; j++)
                    a[j] = As[(j * 8 + ty) * K + kt + k];
                const float* bp = Bs + k * 256 + tx * 8;
                float bb[8];
                #pragma unroll
                for (int i = 0; i < 8; i++) bb[i] = bp[i];
                #pragma unroll
                for (int j = 0; j < 4; j++)
                    #pragma unroll
                    for (int i = 0; i < 8; i++)
                        acc[j][i] = fmaf(a[j], bb[i], acc[j][i]);
            }
        }
        #pragma unroll
        for (int i = 0; i < 8; i++) {
            int c = cbase + tx * 8 + i;
            bool v = c < C;
            float bv = v ? bias[c] : 0.f;
            #pragma unroll
            for (int j = 0; j < 4; j++)
                acc[j][i] = v ? (acc[j][i] + bv) : -FLT_MAX;
        }
        #pragma unroll
        for (int j = 0; j < 4; j++) {
            float tm = acc[j][0];
            #pragma unroll
            for (int i = 1; i < 8; i++) tm = fmaxf(tm, acc[j][i]);
            float nm = fmaxf(m[j], tm);
            float es = 0.f;
            #pragma unroll
            for (int i = 0; i < 8; i++) es += __expf(acc[j][i] - nm);
            s[j] = s[j] * __expf(m[j] - nm) + es;
            m[j] = nm;
            int tl = mytl[j];
            #pragma unroll
            for (int i = 0; i < 8; i++) {
                int c = cbase + tx * 8 + i;
                if (c == tl) lab[j] = acc[j][i];
            }
        }
    }
    #pragma unroll
    for (int j = 0; j < 4; j++) {
        float mw = m[j];
        #pragma unroll
        for (int o = 16; o > 0; o >>= 1) mw = fmaxf(mw, __shfl_xor_sync(0xffffffffu, mw, o));
        float sl = s[j] * __expf(m[j] - mw);
        #pragma unroll
        for (int o = 16; o > 0; o >>= 1) sl += __shfl_xor_sync(0xffffffffu, sl, o);
        float lw = lab[j];
        #pragma unroll
        for (int o = 16; o > 0; o >>= 1) lw = fmaxf(lw, __shfl_xor_sync(0xffffffffu, lw, o));
        if (tx == 0) {
            int g = g0 + j * 8 + ty;
            if (g < n)
                lossout[torig[j * 8 + ty]] = mw + logf(sl) - lw;
        }
    }
}

// ---------------- finalize: combine head splits, mask tails, mean ----------------
__global__ void finalize_kernel(const int* __restrict__ labels, float* __restrict__ out, int ntok)
{
    __shared__ float red[32];
    int tid = threadIdx.x;
    float local = 0.f;
    for (int t = tid; t < ntok; t += blockDim.x) {
        float m0 = g_pm[0][t], m1 = g_pm[1][t];
        float mm = fmaxf(m0, m1);
        float ss = g_ps[0][t] * __expf(m0 - mm) + g_ps[1][t] * __expf(m1 - mm);
        float ll = fmaxf(g_plab[0][t], g_plab[1][t]);
        float loss = mm + logf(ss) - ll;
        int l = labels[t];
        if (l >= C0LO && l < C0HI) loss += g_lt0[t];
        else if (l >= C0HI)        loss += g_lt1[t];
        if (l == 0) loss = 0.f;
        local += loss;
    }
    #pragma unroll
    for (int o = 16; o > 0; o >>= 1) local += __shfl_xor_sync(0xffffffffu, local, o);
    if ((tid & 31) == 0) red[tid >> 5] = local;
    __syncthreads();
    if (tid < 32) {
        float v = red[tid];
        #pragma unroll
        for (int o = 16; o > 0; o >>= 1) v += __shfl_xor_sync(0xffffffffu, v, o);
        if (tid == 0) out[0] = v / (float)ntok;
    }
}

// ---------------- host launch ----------------
extern "C" void kernel_launch(void* const* d_in, const int* in_sizes, int n_in,
                              void* d_out, int out_size)
{
    const float* inp    = (const float*)d_in[0];
    const int*   labels = (const int*)  d_in[1];
    const float* head_W = (const float*)d_in[2];
    const float* head_b = (const float*)d_in[3];
    const float* t0_pW  = (const float*)d_in[4];
    const float* t0_pb  = (const float*)d_in[5];
    const float* t0_W   = (const float*)d_in[6];
    const float* t0_b   = (const float*)d_in[7];
    const float* t1_pW  = (const float*)d_in[8];
    const float* t1_pb  = (const float*)d_in[9];
    const float* t1_W   = (const float*)d_in[10];
    const float* t1_b   = (const float*)d_in[11];
    const int ntok = in_sizes[1];          // 4096

    const int head_smem  = 32 * HID * 2 + 32 * 256 * 4;   // 98304
    const int tail0_smem = 32 * 256 * 4 + 32 * 256 * 4;   // 65536
    const int tail1_smem = 32 * 64 * 4  + 32 * 256 * 4;   // 40960

    cudaFuncSetAttribute(head_kernel, cudaFuncAttributeMaxDynamicSharedMemorySize, head_smem);
    cudaFuncSetAttribute(tail_kernel<256, T0C, 0>, cudaFuncAttributeMaxDynamicSharedMemorySize, tail0_smem);
    cudaFuncSetAttribute(tail_kernel<64,  T1C, 1>, cudaFuncAttributeMaxDynamicSharedMemorySize, tail1_smem);

    gather_kernel<<<1, 256>>>(labels, ntok);
    proj0_kernel<<<(MAXTOK + 7) / 8, 256>>>(inp, t0_pW, t0_pb);
    proj1_kernel<<<(MAXTOK + 7) / 8, 256>>>(inp, t1_pW, t1_pb);
    head_kernel<<<dim3(ntok / 32, 2), 256, head_smem>>>(inp, labels, head_W, head_b);
    tail_kernel<256, T0C, 0><<<(MAXTOK + 31) / 32, 256, tail0_smem>>>(labels, t0_W, t0_b, C0LO);
    tail_kernel<64,  T1C, 1><<<(MAXTOK + 31) / 32, 256, tail1_smem>>>(labels, t1_W, t1_b, C0HI);
    finalize_kernel<<<1, 1024>>>(labels, (float*)d_out, ntok);
}

// round 6
// speedup vs baseline: 7.2749x; 7.2749x over previous
#include <cuda_runtime.h>
#include <cuda_bf16.h>
#include <cfloat>
#include <math.h>
#include <stdint.h>

#define HID    1024
#define HEADC  16002
#define C0LO   16000
#define C0HI   28000
#define P0     256
#define P1     64
#define T0C    12000
#define T1C    8000
#define MAXTOK 4096

#define NTILE   128
#define HTILES  126   // 126*128 = 16128 >= 16002
#define T0TILES 94    // 94*128 = 12032 >= 12000
#define T1TILES 63    // 63*128 = 8064  >= 8000
#define HKC     16    // K chunks of 64 (K=1024)
#define T0KC    4     // K=256
#define T1KC    1     // K=64

#define A_CHUNK 16384   // 128 rows * 128B
#define B_CHUNK 16384   // 128 rows * 128B
#define STAGE   32768
#define CMB_OFF 65536   // 3 * 2048 floats = 24576B
#define MB_OFF  90112
#define RLAB_OFF 90144
#define RORIG_OFF 90656
#define GEMM_SMEM 91168

#define SW128(x) ((x) ^ ((((uint32_t)(x)) >> 3) & 0x70u))

// ---------------- scratch (static device globals; no allocations) ----------------
// NOTE: 1024B alignment is required — uint4 stores and cp.async.bulk need >=16B,
// and the swizzle math assumes 1024B-aligned chunk bases.
__device__ __align__(1024) unsigned char g_Wh[(size_t)HTILES * HKC * B_CHUNK];    // 33 MB
__device__ __align__(1024) unsigned char g_W0[(size_t)T0TILES * T0KC * B_CHUNK];  // 6.2 MB
__device__ __align__(1024) unsigned char g_W1[(size_t)T1TILES * T1KC * B_CHUNK];  // 1.0 MB
__device__ __align__(1024) unsigned char g_Ah[(size_t)32 * HKC * A_CHUNK];        // 8.4 MB
__device__ __align__(1024) unsigned char g_A0[(size_t)32 * T0KC * A_CHUNK];       // 2.1 MB
__device__ __align__(1024) unsigned char g_A1[(size_t)32 * T1KC * A_CHUNK];       // 0.5 MB
__device__ int   g_idx0[MAXTOK];
__device__ int   g_idx1[MAXTOK];
__device__ int   g_cnt[2];
__device__ float g_pt[3][3][4][MAXTOK];  // [kernel][m/s/lab][split][token]

// ---------------- PTX helpers (baseline PTX only; no 'a'-target features) ----------------
__device__ __forceinline__ uint32_t smem_u32(const void* p) {
    uint32_t a;
    asm("{ .reg .u64 t; cvta.to.shared.u64 t, %1; cvt.u32.u64 %0, t; }" : "=r"(a) : "l"(p));
    return a;
}
#define MBARRIER_INIT(addr, cnt) \
    asm volatile("mbarrier.init.shared.b64 [%0], %1;" :: "r"((uint32_t)(addr)), "r"((uint32_t)(cnt)) : "memory")
#define MBARRIER_EXPECT_TX(addr, tx) \
    asm volatile("mbarrier.arrive.expect_tx.shared.b64 _, [%0], %1;" :: "r"((uint32_t)(addr)), "r"((uint32_t)(tx)) : "memory")
#define MBARRIER_ARRIVE(addr) \
    asm volatile("mbarrier.arrive.shared.b64 _, [%0];" :: "r"((uint32_t)(addr)) : "memory")
#define MBARRIER_WAIT(addr, par) do { \
    uint32_t _m = (uint32_t)(addr); uint32_t _p = (uint32_t)(par); uint32_t _d; \
    asm volatile("{\n\t.reg .pred p;\n\t" \
        "mbarrier.try_wait.parity.acquire.cta.shared::cta.b64 p, [%1], %2;\n\t" \
        "selp.b32 %0, 1, 0, p;\n\t}" : "=r"(_d) : "r"(_m), "r"(_p) : "memory"); \
    if (!_d) { \
        asm volatile("{\n\t.reg .pred P1;\n\t" \
            "WL_%=:\n\t" \
            "mbarrier.try_wait.parity.acquire.cta.shared::cta.b64 P1, [%0], %1, 0x989680;\n\t" \
            "@P1 bra.uni WD_%=;\n\t" \
            "bra.uni WL_%=;\n\t" \
            "WD_%=:\n\t}" :: "r"(_m), "r"(_p) : "memory"); \
    } } while (0)

__device__ __forceinline__ void bulk_g2s(uint32_t dst, const void* src, uint32_t bytes, uint32_t mbar) {
    asm volatile("cp.async.bulk.shared::cluster.global.mbarrier::complete_tx::bytes [%0], [%1], %2, [%3];"
        :: "r"(dst), "l"(src), "r"(bytes), "r"(mbar) : "memory");
}
__device__ __forceinline__ void ldsm4(uint32_t* r, uint32_t addr) {
    asm volatile("ldmatrix.sync.aligned.m8n8.x4.shared.b16 {%0,%1,%2,%3}, [%4];"
        : "=r"(r[0]), "=r"(r[1]), "=r"(r[2]), "=r"(r[3]) : "r"(addr));
}
__device__ __forceinline__ void mma16816(float* d, const uint32_t* a, const uint32_t* b) {
    asm volatile("mma.sync.aligned.m16n8k16.row.col.f32.bf16.bf16.f32 "
        "{%0,%1,%2,%3}, {%4,%5,%6,%7}, {%8,%9}, {%0,%1,%2,%3};"
        : "+f"(d[0]), "+f"(d[1]), "+f"(d[2]), "+f"(d[3])
        : "r"(a[0]), "r"(a[1]), "r"(a[2]), "r"(a[3]), "r"(b[0]), "r"(b[1]));
}
__device__ __forceinline__ uint32_t pack_bf2(float a, float b) {
    __nv_bfloat162 h = __floats2bfloat162_rn(a, b);
    return *reinterpret_cast<uint32_t*>(&h);
}

// ---------------- gather tokens per cluster ----------------
__global__ void gather_kernel(const int* __restrict__ labels, int ntok)
{
    __shared__ int c0, c1;
    if (threadIdx.x == 0) { c0 = 0; c1 = 0; }
    __syncthreads();
    for (int i = threadIdx.x; i < ntok; i += blockDim.x) {
        int l = labels[i];
        if (l >= C0LO) {
            if (l < C0HI) g_idx0[atomicAdd(&c0, 1)] = i;
            else          g_idx1[atomicAdd(&c1, 1)] = i;
        }
    }
    __syncthreads();
    if (threadIdx.x == 0) { g_cnt[0] = c0; g_cnt[1] = c1; }
}

// ---------------- convert inp -> bf16 swizzled tiled A (head) ----------------
__global__ void conv_a_kernel(const float* __restrict__ inp)
{
    int idx = blockIdx.x * blockDim.x + threadIdx.x;   // one 16B unit
    if (idx >= MAXTOK * 128) return;
    int token = idx >> 7;
    int unit  = idx & 127;
    int kc = unit >> 3, u = unit & 7;
    const float4* src = reinterpret_cast<const float4*>(inp + (size_t)token * HID + kc * 64 + u * 8);
    float4 v0 = src[0], v1 = src[1];
    uint4 o;
    o.x = pack_bf2(v0.x, v0.y); o.y = pack_bf2(v0.z, v0.w);
    o.z = pack_bf2(v1.x, v1.y); o.w = pack_bf2(v1.z, v1.w);
    int r = token & 127;
    size_t off = ((size_t)(token >> 7) * HKC + kc) * A_CHUNK
               + (r >> 3) * 1024 + SW128((r & 7) * 128 + u * 16);
    *reinterpret_cast<uint4*>(g_Ah + off) = o;
}

// ---------------- convert+transpose W -> bf16 swizzled tiled B ----------------
// W is [K][C] row-major. Output: [tile(128 classes)][kc][128 rows][128B] swizzled.
__global__ void conv_w_kernel(const float* __restrict__ W, int C, int kchunks, int kid)
{
    __shared__ float ws[64][65];
    unsigned char* out = (kid == 0) ? g_Wh : (kid == 1) ? g_W0 : g_W1;
    int ct = blockIdx.x;   // 64-class group
    int kt = blockIdx.y;   // 64-k group == kc
    int tid = threadIdx.x;
    for (int e = tid; e < 64 * 64; e += 256) {
        int kr = e >> 6, cc = e & 63;
        int c = ct * 64 + cc;
        ws[kr][cc] = (c < C) ? W[(size_t)(kt * 64 + kr) * C + c] : 0.f;
    }
    __syncthreads();
    for (int e = tid; e < 512; e += 256) {
        int n64 = e >> 3, u = e & 7;
        int ng = ct * 64 + n64;
        int tile = ng >> 7, nt = ng & 127;
        uint4 o;
        o.x = pack_bf2(ws[u * 8 + 0][n64], ws[u * 8 + 1][n64]);
        o.y = pack_bf2(ws[u * 8 + 2][n64], ws[u * 8 + 3][n64]);
        o.z = pack_bf2(ws[u * 8 + 4][n64], ws[u * 8 + 5][n64]);
        o.w = pack_bf2(ws[u * 8 + 6][n64], ws[u * 8 + 7][n64]);
        size_t off = ((size_t)(tile * kchunks + kt)) * B_CHUNK
                   + (nt >> 3) * 1024 + SW128((nt & 7) * 128 + u * 16);
        *reinterpret_cast<uint4*>(out + off) = o;
    }
}

// ---------------- projections: write bf16 swizzled tiled A for tails ----------------
__global__ void proj0_kernel(const float* __restrict__ inp,
                             const float* __restrict__ pW,
                             const float* __restrict__ pb)
{
    __shared__ float As[8][HID];
    int n = g_cnt[0];
    int g0 = blockIdx.x * 8;
    if (g0 >= n) return;
    int tid = threadIdx.x;
    for (int e = tid; e < 8 * HID; e += 256) {
        int r = e >> 10, k = e & 1023;
        int g = g0 + r;
        As[r][k] = (g < n) ? inp[(size_t)g_idx0[g] * HID + k] : 0.f;
    }
    __syncthreads();
    float acc[8];
    #pragma unroll
    for (int t = 0; t < 8; t++) acc[t] = 0.f;
    float bj = pb[tid];
    #pragma unroll 4
    for (int k = 0; k < HID; k++) {
        float w = pW[k * P0 + tid];
        #pragma unroll
        for (int t = 0; t < 8; t++) acc[t] = fmaf(As[t][k], w, acc[t]);
    }
    int kc = tid >> 6, kk = tid & 63;
    #pragma unroll
    for (int t = 0; t < 8; t++) {
        int g = g0 + t;
        if (g < n) {
            int r = g & 127;
            size_t off = ((size_t)(g >> 7) * T0KC + kc) * A_CHUNK
                       + (r >> 3) * 1024 + SW128((r & 7) * 128 + kk * 2);
            *reinterpret_cast<__nv_bfloat16*>(g_A0 + off) = __float2bfloat16(acc[t] + bj);
        }
    }
}

__global__ void proj1_kernel(const float* __restrict__ inp,
                             const float* __restrict__ pW,
                             const float* __restrict__ pb)
{
    __shared__ float As[8][HID];
    int n = g_cnt[1];
    int g0 = blockIdx.x * 8;
    if (g0 >= n) return;
    int tid = threadIdx.x;
    for (int e = tid; e < 8 * HID; e += 256) {
        int r = e >> 10, k = e & 1023;
        int g = g0 + r;
        As[r][k] = (g < n) ? inp[(size_t)g_idx1[g] * HID + k] : 0.f;
    }
    __syncthreads();
    int j  = tid & 63;
    int tg = tid >> 6;
    float acc0 = 0.f, acc1 = 0.f;
    float bj = pb[j];
    #pragma unroll 4
    for (int k = 0; k < HID; k++) {
        float w = pW[k * P1 + j];
        acc0 = fmaf(As[tg * 2 + 0][k], w, acc0);
        acc1 = fmaf(As[tg * 2 + 1][k], w, acc1);
    }
    #pragma unroll
    for (int t = 0; t < 2; t++) {
        int g = g0 + tg * 2 + t;
        if (g < n) {
            int r = g & 127;
            float v = (t == 0) ? acc0 : acc1;
            size_t off = ((size_t)(g >> 7)) * A_CHUNK
                       + (r >> 3) * 1024 + SW128((r & 7) * 128 + j * 2);
            *reinterpret_cast<__nv_bfloat16*>(g_A1 + off) = __float2bfloat16(v + bj);
        }
    }
}

// ---------------- fused mma.sync GEMM + online logsumexp ----------------
// 8 warps: 2 (m) x 4 (n). Warp tile m64 x n32. CTA tile m128 x n128.
__global__ void __launch_bounds__(256, 1)
gemm_ce_kernel(const float* __restrict__ bias, const int* __restrict__ labels,
               int C, int kchunks, int tiles_total, int kid, int lo)
{
    if (kid != 0) {
        if ((int)blockIdx.x * 128 >= g_cnt[kid - 1]) return;
    }
    extern __shared__ unsigned char sm[];
    uint32_t sb = smem_u32(sm);
    const int tid = threadIdx.x, wid = tid >> 5, lane = tid & 31;
    const int wm = wid >> 2, wn = wid & 3;
    const int tq = lane >> 2, tc = lane & 3;
    const int mblock = blockIdx.x, split = blockIdx.y;

    const unsigned char* Asw = (kid == 0) ? g_Ah : (kid == 1) ? g_A0 : g_A1;
    const unsigned char* Bsw = (kid == 0) ? g_Wh : (kid == 1) ? g_W0 : g_W1;

    // split tile range
    const int q4 = tiles_total >> 2, rem = tiles_total & 3;
    const int tbeg = split * q4 + min(split, rem);
    const int tcnt = q4 + (split < rem ? 1 : 0);

    const uint32_t full0  = sb + MB_OFF,      full1  = sb + MB_OFF + 8;
    const uint32_t empty0 = sb + MB_OFF + 16, empty1 = sb + MB_OFF + 24;
    int* rlabs = reinterpret_cast<int*>(sm + RLAB_OFF);
    int* rorig = reinterpret_cast<int*>(sm + RORIG_OFF);

    if (tid == 0) {
        MBARRIER_INIT(full0, 1);    MBARRIER_INIT(full1, 1);
        MBARRIER_INIT(empty0, 256); MBARRIER_INIT(empty1, 256);
    }
    if (tid < 128) {
        if (kid == 0) {
            int orig = mblock * 128 + tid;
            int l = labels[orig];
            rlabs[tid] = (l < C0LO) ? l : ((l < C0HI) ? C0LO : C0LO + 1);
            rorig[tid] = orig;
        } else {
            int n = g_cnt[kid - 1];
            int g = mblock * 128 + tid;
            if (g < n) {
                int o = ((kid == 1) ? g_idx0 : g_idx1)[g];
                rorig[tid] = o; rlabs[tid] = labels[o] - lo;
            } else { rorig[tid] = -1; rlabs[tid] = -2; }
        }
    }
    __syncthreads();

    const int total = tcnt * kchunks;
    if (tid == 0) {
        #pragma unroll 1
        for (int pc = 0; pc < 2 && pc < total; pc++) {
            uint32_t fb = pc ? full1 : full0;
            int tile = tbeg + pc / kchunks, kc = pc % kchunks;
            MBARRIER_EXPECT_TX(fb, A_CHUNK + B_CHUNK);
            bulk_g2s(sb + pc * STAGE, Asw + ((size_t)mblock * kchunks + kc) * A_CHUNK, A_CHUNK, fb);
            bulk_g2s(sb + pc * STAGE + A_CHUNK, Bsw + ((size_t)tile * kchunks + kc) * B_CHUNK, B_CHUNK, fb);
        }
    }

    // per-thread ldmatrix offsets
    const int sub = lane >> 3, li = lane & 7;
    const uint32_t vx = (uint32_t)li << 4;
    uint32_t aoff[4], boff[2];
    {
        int arowadd = (sub & 1) * 8;
        #pragma unroll
        for (int mt = 0; mt < 4; mt++) {
            int row = wm * 64 + mt * 16 + arowadd + li;
            aoff[mt] = ((uint32_t)(row >> 3) << 10) + ((uint32_t)li << 7);
        }
        int browadd = (sub >> 1) * 8;
        #pragma unroll
        for (int nb = 0; nb < 2; nb++) {
            int row = wn * 32 + nb * 16 + browadd + li;
            boff[nb] = ((uint32_t)(row >> 3) << 10) + ((uint32_t)li << 7);
        }
    }
    const uint32_t auo = (uint32_t)(sub >> 1) << 4;
    const uint32_t buo = (uint32_t)(sub & 1) << 4;

    // running state per (mtile, half)
    float rm[4][2], rs[4][2], rl[4][2];
    int rlb[4][2];
    #pragma unroll
    for (int mt = 0; mt < 4; mt++)
        #pragma unroll
        for (int h = 0; h < 2; h++) {
            rm[mt][h] = -FLT_MAX; rs[mt][h] = 0.f; rl[mt][h] = -FLT_MAX;
            rlb[mt][h] = rlabs[wm * 64 + mt * 16 + tq + h * 8];
        }

    int cc = 0;
    #pragma unroll 1
    for (int tt = 0; tt < tcnt; tt++) {
        float acc[4][4][4];
        #pragma unroll
        for (int mt = 0; mt < 4; mt++)
            #pragma unroll
            for (int nt = 0; nt < 4; nt++)
                #pragma unroll
                for (int e = 0; e < 4; e++) acc[mt][nt][e] = 0.f;

        #pragma unroll 1
        for (int kc = 0; kc < kchunks; kc++, cc++) {
            const int st = cc & 1, u = cc >> 1;
            const uint32_t fb = st ? full1 : full0;
            const uint32_t eb = st ? empty1 : empty0;
            MBARRIER_WAIT(fb, u & 1);
            const uint32_t Ab = sb + st * STAGE;
            const uint32_t Bb = Ab + A_CHUNK;
            #pragma unroll
            for (int ks = 0; ks < 4; ks++) {
                const uint32_t kx = (uint32_t)ks << 5;
                uint32_t a[4][4], bfr[4][2];
                #pragma unroll
                for (int mt = 0; mt < 4; mt++)
                    ldsm4(a[mt], Ab + aoff[mt] + ((kx + auo) ^ vx));
                #pragma unroll
                for (int nb = 0; nb < 2; nb++) {
                    uint32_t t4[4];
                    ldsm4(t4, Bb + boff[nb] + ((kx + buo) ^ vx));
                    bfr[nb * 2 + 0][0] = t4[0]; bfr[nb * 2 + 0][1] = t4[1];
                    bfr[nb * 2 + 1][0] = t4[2]; bfr[nb * 2 + 1][1] = t4[3];
                }
                #pragma unroll
                for (int mt = 0; mt < 4; mt++)
                    #pragma unroll
                    for (int nt = 0; nt < 4; nt++)
                        mma16816(acc[mt][nt], a[mt], bfr[nt]);
            }
            MBARRIER_ARRIVE(eb);
            if (tid == 0 && cc + 2 < total) {
                MBARRIER_WAIT(eb, u & 1);
                int nc = cc + 2;
                int ntile = tbeg + nc / kchunks, nkc = nc % kchunks;
                MBARRIER_EXPECT_TX(fb, A_CHUNK + B_CHUNK);
                bulk_g2s(sb + st * STAGE, Asw + ((size_t)mblock * kchunks + nkc) * A_CHUNK, A_CHUNK, fb);
                bulk_g2s(sb + st * STAGE + A_CHUNK, Bsw + ((size_t)ntile * kchunks + nkc) * B_CHUNK, B_CHUNK, fb);
            }
        }
        // ---- epilogue for this tile (online logsumexp, register-resident) ----
        const int cb0 = (tbeg + tt) * NTILE + wn * 32 + tc * 2;
        #pragma unroll
        for (int mt = 0; mt < 4; mt++)
            #pragma unroll
            for (int h = 0; h < 2; h++) {
                float v[8];
                float tmax = -FLT_MAX;
                #pragma unroll
                for (int nt = 0; nt < 4; nt++)
                    #pragma unroll
                    for (int e = 0; e < 2; e++) {
                        int c = cb0 + nt * 8 + e;
                        float x = -FLT_MAX;
                        if (c < C) x = acc[mt][nt][h * 2 + e] + __ldg(bias + c);
                        v[nt * 2 + e] = x;
                        tmax = fmaxf(tmax, x);
                        if (c == rlb[mt][h]) rl[mt][h] = x;
                    }
                float nm = fmaxf(rm[mt][h], tmax);
                if (nm > -1e37f) {
                    float ssum = rs[mt][h] * __expf(rm[mt][h] - nm);
                    #pragma unroll
                    for (int qq = 0; qq < 8; qq++) ssum += __expf(v[qq] - nm);
                    rs[mt][h] = ssum; rm[mt][h] = nm;
                }
            }
    }

    // ---- cross-warp combine (16 partials per row) ----
    float* cm = reinterpret_cast<float*>(sm + CMB_OFF);
    float* cs = cm + 2048;
    float* cl = cm + 4096;
    #pragma unroll
    for (int mt = 0; mt < 4; mt++)
        #pragma unroll
        for (int h = 0; h < 2; h++) {
            int r = wm * 64 + mt * 16 + tq + h * 8;
            int p = wn * 4 + tc;
            cm[r * 16 + p] = rm[mt][h];
            cs[r * 16 + p] = rs[mt][h];
            cl[r * 16 + p] = rl[mt][h];
        }
    __syncthreads();
    if (tid < 128) {
        int r = tid;
        float M = -FLT_MAX, L = -FLT_MAX;
        #pragma unroll 4
        for (int p = 0; p < 16; p++) {
            M = fmaxf(M, cm[r * 16 + p]);
            L = fmaxf(L, cl[r * 16 + p]);
        }
        float S = 0.f;
        #pragma unroll 4
        for (int p = 0; p < 16; p++) {
            float mm = cm[r * 16 + p];
            if (mm > -1e37f) S += cs[r * 16 + p] * __expf(mm - M);
        }
        int orig = rorig[r];
        if (orig >= 0) {
            g_pt[kid][0][split][orig] = M;
            g_pt[kid][1][split][orig] = S;
            g_pt[kid][2][split][orig] = L;
        }
    }
}

// ---------------- finalize: combine splits, mask, mean ----------------
__device__ __forceinline__ float lse4(const float* mm, const float* ss) {
    float M = fmaxf(fmaxf(mm[0], mm[1]), fmaxf(mm[2], mm[3]));
    float S = ss[0] * __expf(mm[0] - M) + ss[1] * __expf(mm[1] - M)
            + ss[2] * __expf(mm[2] - M) + ss[3] * __expf(mm[3] - M);
    return M + logf(S);
}

__global__ void finalize_kernel(const int* __restrict__ labels, float* __restrict__ out, int ntok)
{
    __shared__ float red[32];
    int tid = threadIdx.x;
    float local = 0.f;
    for (int t = tid; t < ntok; t += blockDim.x) {
        float hm[4], hs[4], hl = -FLT_MAX;
        #pragma unroll
        for (int s = 0; s < 4; s++) {
            hm[s] = g_pt[0][0][s][t];
            hs[s] = g_pt[0][1][s][t];
            hl = fmaxf(hl, g_pt[0][2][s][t]);
        }
        float loss = lse4(hm, hs) - hl;
        int l = labels[t];
        if (l >= C0LO) {
            int kid = (l < C0HI) ? 1 : 2;
            float tm[4], ts[4], tl = -FLT_MAX;
            #pragma unroll
            for (int s = 0; s < 4; s++) {
                tm[s] = g_pt[kid][0][s][t];
                ts[s] = g_pt[kid][1][s][t];
                tl = fmaxf(tl, g_pt[kid][2][s][t]);
            }
            loss += lse4(tm, ts) - tl;
        }
        if (l == 0) loss = 0.f;
        local += loss;
    }
    #pragma unroll
    for (int o = 16; o > 0; o >>= 1) local += __shfl_xor_sync(0xffffffffu, local, o);
    if ((tid & 31) == 0) red[tid >> 5] = local;
    __syncthreads();
    if (tid < 32) {
        float v = red[tid];
        #pragma unroll
        for (int o = 16; o > 0; o >>= 1) v += __shfl_xor_sync(0xffffffffu, v, o);
        if (tid == 0) out[0] = v / (float)ntok;
    }
}

// ---------------- host launch ----------------
extern "C" void kernel_launch(void* const* d_in, const int* in_sizes, int n_in,
                              void* d_out, int out_size)
{
    const float* inp    = (const float*)d_in[0];
    const int*   labels = (const int*)  d_in[1];
    const float* head_W = (const float*)d_in[2];
    const float* head_b = (const float*)d_in[3];
    const float* t0_pW  = (const float*)d_in[4];
    const float* t0_pb  = (const float*)d_in[5];
    const float* t0_W   = (const float*)d_in[6];
    const float* t0_b   = (const float*)d_in[7];
    const float* t1_pW  = (const float*)d_in[8];
    const float* t1_pb  = (const float*)d_in[9];
    const float* t1_W   = (const float*)d_in[10];
    const float* t1_b   = (const float*)d_in[11];
    const int ntok = in_sizes[1];   // 4096

    cudaFuncSetAttribute(gemm_ce_kernel, cudaFuncAttributeMaxDynamicSharedMemorySize, GEMM_SMEM);

    gather_kernel<<<1, 256>>>(labels, ntok);
    conv_a_kernel<<<(MAXTOK * 128 + 255) / 256, 256>>>(inp);
    conv_w_kernel<<<dim3(HTILES * 2, HKC), 256>>>(head_W, HEADC, HKC, 0);
    conv_w_kernel<<<dim3(T0TILES * 2, T0KC), 256>>>(t0_W, T0C, T0KC, 1);
    conv_w_kernel<<<dim3(T1TILES * 2, T1KC), 256>>>(t1_W, T1C, T1KC, 2);
    proj0_kernel<<<(MAXTOK + 7) / 8, 256>>>(inp, t0_pW, t0_pb);
    proj1_kernel<<<(MAXTOK + 7) / 8, 256>>>(inp, t1_pW, t1_pb);

    gemm_ce_kernel<<<dim3(ntok / 128, 4), 256, GEMM_SMEM>>>(head_b, labels, HEADC, HKC, HTILES, 0, 0);
    gemm_ce_kernel<<<dim3(32, 4), 256, GEMM_SMEM>>>(t0_b, labels, T0C, T0KC, T0TILES, 1, C0LO);
    gemm_ce_kernel<<<dim3(32, 4), 256, GEMM_SMEM>>>(t1_b, labels, T1C, T1KC, T1TILES, 2, C0HI);
    finalize_kernel<<<1, 1024>>>(labels, (float*)d_out, ntok);
}

// round 7
// speedup vs baseline: 7.8641x; 1.0810x over previous
#include <cuda_runtime.h>
#include <cuda_bf16.h>
#include <cfloat>
#include <math.h>
#include <stdint.h>

#define HID    1024
#define HEADC  16002
#define C0LO   16000
#define C0HI   28000
#define P0     256
#define P1     64
#define T0C    12000
#define T1C    8000
#define MAXTOK 4096

#define NTILE   128
#define HTILES  126   // 126*128 = 16128 >= 16002
#define T0TILES 94    // 94*128 = 12032 >= 12000
#define T1TILES 63    // 63*128 = 8064  >= 8000
#define HKC     16    // K chunks of 64 (K=1024)
#define T0KC    4     // K=256
#define T1KC    1     // K=64

#define A_CHUNK 16384   // 128 rows * 128B
#define B_CHUNK 16384   // 128 rows * 128B
#define STAGE   32768
#define NSTAGE  4
#define CMB_OFF   131072  // 3 * 2048 floats = 24576B
#define MB_OFF    155648  // 4 full + 4 empty mbarriers = 64B
#define RLAB_OFF  155712
#define RORIG_OFF 156224
#define GEMM_SMEM 156736

#define SW128(x) ((x) ^ ((((uint32_t)(x)) >> 3) & 0x70u))

// ---------------- scratch (static device globals; no allocations) ----------------
__device__ __align__(1024) unsigned char g_Wh[(size_t)HTILES * HKC * B_CHUNK];    // 33 MB
__device__ __align__(1024) unsigned char g_W0[(size_t)T0TILES * T0KC * B_CHUNK];  // 6.2 MB
__device__ __align__(1024) unsigned char g_W1[(size_t)T1TILES * T1KC * B_CHUNK];  // 1.0 MB
__device__ __align__(1024) unsigned char g_Ah[(size_t)32 * HKC * A_CHUNK];        // 8.4 MB
__device__ __align__(1024) unsigned char g_A0[(size_t)32 * T0KC * A_CHUNK];       // 2.1 MB
__device__ __align__(1024) unsigned char g_A1[(size_t)32 * T1KC * A_CHUNK];       // 0.5 MB
__device__ int   g_idx0[MAXTOK];
__device__ int   g_idx1[MAXTOK];
__device__ int   g_cnt[2];
__device__ float g_pt[3][3][4][MAXTOK];  // [kernel][m/s/lab][split][token]

// ---------------- PTX helpers (baseline PTX only; no 'a'-target features) ----------------
__device__ __forceinline__ uint32_t smem_u32(const void* p) {
    uint32_t a;
    asm("{ .reg .u64 t; cvta.to.shared.u64 t, %1; cvt.u32.u64 %0, t; }" : "=r"(a) : "l"(p));
    return a;
}
#define MBARRIER_INIT(addr, cnt) \
    asm volatile("mbarrier.init.shared.b64 [%0], %1;" :: "r"((uint32_t)(addr)), "r"((uint32_t)(cnt)) : "memory")
#define MBARRIER_EXPECT_TX(addr, tx) \
    asm volatile("mbarrier.arrive.expect_tx.shared.b64 _, [%0], %1;" :: "r"((uint32_t)(addr)), "r"((uint32_t)(tx)) : "memory")
#define MBARRIER_ARRIVE(addr) \
    asm volatile("mbarrier.arrive.shared.b64 _, [%0];" :: "r"((uint32_t)(addr)) : "memory")
#define MBARRIER_WAIT(addr, par) do { \
    uint32_t _m = (uint32_t)(addr); uint32_t _p = (uint32_t)(par); uint32_t _d; \
    asm volatile("{\n\t.reg .pred p;\n\t" \
        "mbarrier.try_wait.parity.acquire.cta.shared::cta.b64 p, [%1], %2;\n\t" \
        "selp.b32 %0, 1, 0, p;\n\t}" : "=r"(_d) : "r"(_m), "r"(_p) : "memory"); \
    if (!_d) { \
        asm volatile("{\n\t.reg .pred P1;\n\t" \
            "WL_%=:\n\t" \
            "mbarrier.try_wait.parity.acquire.cta.shared::cta.b64 P1, [%0], %1, 0x989680;\n\t" \
            "@P1 bra.uni WD_%=;\n\t" \
            "bra.uni WL_%=;\n\t" \
            "WD_%=:\n\t}" :: "r"(_m), "r"(_p) : "memory"); \
    } } while (0)

__device__ __forceinline__ void bulk_g2s(uint32_t dst, const void* src, uint32_t bytes, uint32_t mbar) {
    asm volatile("cp.async.bulk.shared::cluster.global.mbarrier::complete_tx::bytes [%0], [%1], %2, [%3];"
        :: "r"(dst), "l"(src), "r"(bytes), "r"(mbar) : "memory");
}
__device__ __forceinline__ void ldsm4(uint32_t* r, uint32_t addr) {
    asm volatile("ldmatrix.sync.aligned.m8n8.x4.shared.b16 {%0,%1,%2,%3}, [%4];"
        : "=r"(r[0]), "=r"(r[1]), "=r"(r[2]), "=r"(r[3]) : "r"(addr));
}
__device__ __forceinline__ void mma16816(float* d, const uint32_t* a, const uint32_t* b) {
    asm volatile("mma.sync.aligned.m16n8k16.row.col.f32.bf16.bf16.f32 "
        "{%0,%1,%2,%3}, {%4,%5,%6,%7}, {%8,%9}, {%0,%1,%2,%3};"
        : "+f"(d[0]), "+f"(d[1]), "+f"(d[2]), "+f"(d[3])
        : "r"(a[0]), "r"(a[1]), "r"(a[2]), "r"(a[3]), "r"(b[0]), "r"(b[1]));
}
__device__ __forceinline__ uint32_t pack_bf2(float a, float b) {
    __nv_bfloat162 h = __floats2bfloat162_rn(a, b);
    return *reinterpret_cast<uint32_t*>(&h);
}

// ---------------- gather tokens per cluster ----------------
__global__ void gather_kernel(const int* __restrict__ labels, int ntok)
{
    __shared__ int c0, c1;
    if (threadIdx.x == 0) { c0 = 0; c1 = 0; }
    __syncthreads();
    for (int i = threadIdx.x; i < ntok; i += blockDim.x) {
        int l = labels[i];
        if (l >= C0LO) {
            if (l < C0HI) g_idx0[atomicAdd(&c0, 1)] = i;
            else          g_idx1[atomicAdd(&c1, 1)] = i;
        }
    }
    __syncthreads();
    if (threadIdx.x == 0) { g_cnt[0] = c0; g_cnt[1] = c1; }
}

// ---------------- convert inp -> bf16 swizzled tiled A (head) ----------------
__global__ void conv_a_kernel(const float* __restrict__ inp)
{
    int idx = blockIdx.x * blockDim.x + threadIdx.x;   // one 16B unit
    if (idx >= MAXTOK * 128) return;
    int token = idx >> 7;
    int unit  = idx & 127;
    int kc = unit >> 3, u = unit & 7;
    const float4* src = reinterpret_cast<const float4*>(inp + (size_t)token * HID + kc * 64 + u * 8);
    float4 v0 = src[0], v1 = src[1];
    uint4 o;
    o.x = pack_bf2(v0.x, v0.y); o.y = pack_bf2(v0.z, v0.w);
    o.z = pack_bf2(v1.x, v1.y); o.w = pack_bf2(v1.z, v1.w);
    int r = token & 127;
    size_t off = ((size_t)(token >> 7) * HKC + kc) * A_CHUNK
               + (r >> 3) * 1024 + SW128((r & 7) * 128 + u * 16);
    *reinterpret_cast<uint4*>(g_Ah + off) = o;
}

// ---------------- convert+transpose W -> bf16 swizzled tiled B ----------------
// W is [K][C] row-major. Output: [tile(128 classes)][kc][128 rows][128B] swizzled.
__global__ void conv_w_kernel(const float* __restrict__ W, int C, int kchunks, int kid)
{
    __shared__ float ws[64][65];
    unsigned char* out = (kid == 0) ? g_Wh : (kid == 1) ? g_W0 : g_W1;
    int ct = blockIdx.x;   // 64-class group
    int kt = blockIdx.y;   // 64-k group == kc
    int tid = threadIdx.x;
    for (int e = tid; e < 64 * 64; e += 256) {
        int kr = e >> 6, cc = e & 63;
        int c = ct * 64 + cc;
        ws[kr][cc] = (c < C) ? W[(size_t)(kt * 64 + kr) * C + c] : 0.f;
    }
    __syncthreads();
    for (int e = tid; e < 512; e += 256) {
        int n64 = e >> 3, u = e & 7;
        int ng = ct * 64 + n64;
        int tile = ng >> 7, nt = ng & 127;
        uint4 o;
        o.x = pack_bf2(ws[u * 8 + 0][n64], ws[u * 8 + 1][n64]);
        o.y = pack_bf2(ws[u * 8 + 2][n64], ws[u * 8 + 3][n64]);
        o.z = pack_bf2(ws[u * 8 + 4][n64], ws[u * 8 + 5][n64]);
        o.w = pack_bf2(ws[u * 8 + 6][n64], ws[u * 8 + 7][n64]);
        size_t off = ((size_t)(tile * kchunks + kt)) * B_CHUNK
                   + (nt >> 3) * 1024 + SW128((nt & 7) * 128 + u * 16);
        *reinterpret_cast<uint4*>(out + off) = o;
    }
}

// ---------------- projections: write bf16 swizzled tiled A for tails ----------------
__global__ void proj0_kernel(const float* __restrict__ inp,
                             const float* __restrict__ pW,
                             const float* __restrict__ pb)
{
    __shared__ float As[8][HID];
    int n = g_cnt[0];
    int g0 = blockIdx.x * 8;
    if (g0 >= n) return;
    int tid = threadIdx.x;
    for (int e = tid; e < 8 * HID; e += 256) {
        int r = e >> 10, k = e & 1023;
        int g = g0 + r;
        As[r][k] = (g < n) ? inp[(size_t)g_idx0[g] * HID + k] : 0.f;
    }
    __syncthreads();
    float acc[8];
    #pragma unroll
    for (int t = 0; t < 8; t++) acc[t] = 0.f;
    float bj = pb[tid];
    #pragma unroll 4
    for (int k = 0; k < HID; k++) {
        float w = pW[k * P0 + tid];
        #pragma unroll
        for (int t = 0; t < 8; t++) acc[t] = fmaf(As[t][k], w, acc[t]);
    }
    int kc = tid >> 6, kk = tid & 63;
    #pragma unroll
    for (int t = 0; t < 8; t++) {
        int g = g0 + t;
        if (g < n) {
            int r = g & 127;
            size_t off = ((size_t)(g >> 7) * T0KC + kc) * A_CHUNK
                       + (r >> 3) * 1024 + SW128((r & 7) * 128 + kk * 2);
            *reinterpret_cast<__nv_bfloat16*>(g_A0 + off) = __float2bfloat16(acc[t] + bj);
        }
    }
}

__global__ void proj1_kernel(const float* __restrict__ inp,
                             const float* __restrict__ pW,
                             const float* __restrict__ pb)
{
    __shared__ float As[8][HID];
    int n = g_cnt[1];
    int g0 = blockIdx.x * 8;
    if (g0 >= n) return;
    int tid = threadIdx.x;
    for (int e = tid; e < 8 * HID; e += 256) {
        int r = e >> 10, k = e & 1023;
        int g = g0 + r;
        As[r][k] = (g < n) ? inp[(size_t)g_idx1[g] * HID + k] : 0.f;
    }
    __syncthreads();
    int j  = tid & 63;
    int tg = tid >> 6;
    float acc0 = 0.f, acc1 = 0.f;
    float bj = pb[j];
    #pragma unroll 4
    for (int k = 0; k < HID; k++) {
        float w = pW[k * P1 + j];
        acc0 = fmaf(As[tg * 2 + 0][k], w, acc0);
        acc1 = fmaf(As[tg * 2 + 1][k], w, acc1);
    }
    #pragma unroll
    for (int t = 0; t < 2; t++) {
        int g = g0 + tg * 2 + t;
        if (g < n) {
            int r = g & 127;
            float v = (t == 0) ? acc0 : acc1;
            size_t off = ((size_t)(g >> 7)) * A_CHUNK
                       + (r >> 3) * 1024 + SW128((r & 7) * 128 + j * 2);
            *reinterpret_cast<__nv_bfloat16*>(g_A1 + off) = __float2bfloat16(v + bj);
        }
    }
}

// ---------------- fused mma.sync GEMM + online logsumexp ----------------
// 8 MMA warps: 2 (m) x 4 (n), warp tile m64 x n32, CTA tile m128 x n128.
// Warp 8: dedicated producer (1 elected thread) feeding a 4-stage ring.
__global__ void __launch_bounds__(288, 1)
gemm_ce_kernel(const float* __restrict__ bias, const int* __restrict__ labels,
               int C, int kchunks, int tiles_total, int kid, int lo)
{
    if (kid != 0) {
        if ((int)blockIdx.x * 128 >= g_cnt[kid - 1]) return;
    }
    extern __shared__ unsigned char sm[];
    uint32_t sb = smem_u32(sm);
    const int tid = threadIdx.x, wid = tid >> 5, lane = tid & 31;
    const int mblock = blockIdx.x, split = blockIdx.y;

    const unsigned char* Asw = (kid == 0) ? g_Ah : (kid == 1) ? g_A0 : g_A1;
    const unsigned char* Bsw = (kid == 0) ? g_Wh : (kid == 1) ? g_W0 : g_W1;

    // split tile range
    const int q4 = tiles_total >> 2, rem = tiles_total & 3;
    const int tbeg = split * q4 + min(split, rem);
    const int tcnt = q4 + (split < rem ? 1 : 0);
    const int total = tcnt * kchunks;

    int* rlabs = reinterpret_cast<int*>(sm + RLAB_OFF);
    int* rorig = reinterpret_cast<int*>(sm + RORIG_OFF);

    if (tid == 0) {
        #pragma unroll
        for (int s = 0; s < NSTAGE; s++) {
            MBARRIER_INIT(sb + MB_OFF + s * 8, 1);         // full[s]
            MBARRIER_INIT(sb + MB_OFF + 32 + s * 8, 256);  // empty[s]
        }
    }
    if (tid < 128) {
        if (kid == 0) {
            int orig = mblock * 128 + tid;
            int l = labels[orig];
            rlabs[tid] = (l < C0LO) ? l : ((l < C0HI) ? C0LO : C0LO + 1);
            rorig[tid] = orig;
        } else {
            int n = g_cnt[kid - 1];
            int g = mblock * 128 + tid;
            if (g < n) {
                int o = ((kid == 1) ? g_idx0 : g_idx1)[g];
                rorig[tid] = o; rlabs[tid] = labels[o] - lo;
            } else { rorig[tid] = -1; rlabs[tid] = -2; }
        }
    }
    __syncthreads();

    if (wid == 8) {
        // ---------------- dedicated producer ----------------
        if (lane == 0) {
            #pragma unroll 1
            for (int cc = 0; cc < total; cc++) {
                int st = cc & (NSTAGE - 1), ph = cc >> 2;
                uint32_t fb = sb + MB_OFF + st * 8;
                uint32_t eb = sb + MB_OFF + 32 + st * 8;
                if (cc >= NSTAGE) MBARRIER_WAIT(eb, (ph - 1) & 1);
                MBARRIER_EXPECT_TX(fb, A_CHUNK + B_CHUNK);
                int tile = tbeg + cc / kchunks, kc = cc % kchunks;
                bulk_g2s(sb + st * STAGE, Asw + ((size_t)mblock * kchunks + kc) * A_CHUNK, A_CHUNK, fb);
                bulk_g2s(sb + st * STAGE + A_CHUNK, Bsw + ((size_t)tile * kchunks + kc) * B_CHUNK, B_CHUNK, fb);
            }
        }
    } else {
        // ---------------- MMA consumers ----------------
        const int wm = wid >> 2, wn = wid & 3;
        const int tq = lane >> 2, tc = lane & 3;

        // per-thread ldmatrix offsets
        const int sub = lane >> 3, li = lane & 7;
        const uint32_t vx = (uint32_t)li << 4;
        uint32_t aoff[4], boff[2];
        {
            int arowadd = (sub & 1) * 8;
            #pragma unroll
            for (int mt = 0; mt < 4; mt++) {
                int row = wm * 64 + mt * 16 + arowadd + li;
                aoff[mt] = ((uint32_t)(row >> 3) << 10) + ((uint32_t)li << 7);
            }
            int browadd = (sub >> 1) * 8;
            #pragma unroll
            for (int nb = 0; nb < 2; nb++) {
                int row = wn * 32 + nb * 16 + browadd + li;
                boff[nb] = ((uint32_t)(row >> 3) << 10) + ((uint32_t)li << 7);
            }
        }
        const uint32_t auo = (uint32_t)(sub >> 1) << 4;
        const uint32_t buo = (uint32_t)(sub & 1) << 4;

        // running state per (mtile, half)
        float rm[4][2], rs[4][2], rl[4][2];
        int rlb[4][2];
        #pragma unroll
        for (int mt = 0; mt < 4; mt++)
            #pragma unroll
            for (int h = 0; h < 2; h++) {
                rm[mt][h] = -FLT_MAX; rs[mt][h] = 0.f; rl[mt][h] = -FLT_MAX;
                rlb[mt][h] = rlabs[wm * 64 + mt * 16 + tq + h * 8];
            }

        int cc = 0;
        #pragma unroll 1
        for (int tt = 0; tt < tcnt; tt++) {
            float acc[4][4][4];
            #pragma unroll
            for (int mt = 0; mt < 4; mt++)
                #pragma unroll
                for (int nt = 0; nt < 4; nt++)
                    #pragma unroll
                    for (int e = 0; e < 4; e++) acc[mt][nt][e] = 0.f;

            #pragma unroll 1
            for (int kc = 0; kc < kchunks; kc++, cc++) {
                const int st = cc & (NSTAGE - 1), ph = cc >> 2;
                const uint32_t fb = sb + MB_OFF + st * 8;
                const uint32_t eb = sb + MB_OFF + 32 + st * 8;
                MBARRIER_WAIT(fb, ph & 1);
                const uint32_t Ab = sb + st * STAGE;
                const uint32_t Bb = Ab + A_CHUNK;
                #pragma unroll
                for (int ks = 0; ks < 4; ks++) {
                    const uint32_t kx = (uint32_t)ks << 5;
                    uint32_t a[4][4], bfr[4][2];
                    #pragma unroll
                    for (int mt = 0; mt < 4; mt++)
                        ldsm4(a[mt], Ab + aoff[mt] + ((kx + auo) ^ vx));
                    #pragma unroll
                    for (int nb = 0; nb < 2; nb++) {
                        uint32_t t4[4];
                        ldsm4(t4, Bb + boff[nb] + ((kx + buo) ^ vx));
                        bfr[nb * 2 + 0][0] = t4[0]; bfr[nb * 2 + 0][1] = t4[1];
                        bfr[nb * 2 + 1][0] = t4[2]; bfr[nb * 2 + 1][1] = t4[3];
                    }
                    #pragma unroll
                    for (int mt = 0; mt < 4; mt++)
                        #pragma unroll
                        for (int nt = 0; nt < 4; nt++)
                            mma16816(acc[mt][nt], a[mt], bfr[nt]);
                }
                MBARRIER_ARRIVE(eb);
            }
            // ---- epilogue for this tile (online logsumexp, register-resident) ----
            const int cb0 = (tbeg + tt) * NTILE + wn * 32 + tc * 2;
            #pragma unroll
            for (int mt = 0; mt < 4; mt++)
                #pragma unroll
                for (int h = 0; h < 2; h++) {
                    float v[8];
                    float tmax = -FLT_MAX;
                    #pragma unroll
                    for (int nt = 0; nt < 4; nt++)
                        #pragma unroll
                        for (int e = 0; e < 2; e++) {
                            int c = cb0 + nt * 8 + e;
                            float x = -FLT_MAX;
                            if (c < C) x = acc[mt][nt][h * 2 + e] + __ldg(bias + c);
                            v[nt * 2 + e] = x;
                            tmax = fmaxf(tmax, x);
                            if (c == rlb[mt][h]) rl[mt][h] = x;
                        }
                    float nm = fmaxf(rm[mt][h], tmax);
                    if (nm > -1e37f) {
                        float ssum = rs[mt][h] * __expf(rm[mt][h] - nm);
                        #pragma unroll
                        for (int qq = 0; qq < 8; qq++) ssum += __expf(v[qq] - nm);
                        rs[mt][h] = ssum; rm[mt][h] = nm;
                    }
                }
        }

        // ---- stash partials (16 per row) ----
        float* cm = reinterpret_cast<float*>(sm + CMB_OFF);
        float* cs = cm + 2048;
        float* cl = cm + 4096;
        #pragma unroll
        for (int mt = 0; mt < 4; mt++)
            #pragma unroll
            for (int h = 0; h < 2; h++) {
                int r = wm * 64 + mt * 16 + tq + h * 8;
                int p = wn * 4 + tc;
                cm[r * 16 + p] = rm[mt][h];
                cs[r * 16 + p] = rs[mt][h];
                cl[r * 16 + p] = rl[mt][h];
            }
    }
    __syncthreads();
    if (tid < 128) {
        float* cm = reinterpret_cast<float*>(sm + CMB_OFF);
        float* cs = cm + 2048;
        float* cl = cm + 4096;
        int r = tid;
        float M = -FLT_MAX, L = -FLT_MAX;
        #pragma unroll 4
        for (int p = 0; p < 16; p++) {
            M = fmaxf(M, cm[r * 16 + p]);
            L = fmaxf(L, cl[r * 16 + p]);
        }
        float S = 0.f;
        #pragma unroll 4
        for (int p = 0; p < 16; p++) {
            float mm = cm[r * 16 + p];
            if (mm > -1e37f) S += cs[r * 16 + p] * __expf(mm - M);
        }
        int orig = rorig[r];
        if (orig >= 0) {
            g_pt[kid][0][split][orig] = M;
            g_pt[kid][1][split][orig] = S;
            g_pt[kid][2][split][orig] = L;
        }
    }
}

// ---------------- finalize: combine splits, mask, mean ----------------
__device__ __forceinline__ float lse4(const float* mm, const float* ss) {
    float M = fmaxf(fmaxf(mm[0], mm[1]), fmaxf(mm[2], mm[3]));
    float S = ss[0] * __expf(mm[0] - M) + ss[1] * __expf(mm[1] - M)
            + ss[2] * __expf(mm[2] - M) + ss[3] * __expf(mm[3] - M);
    return M + logf(S);
}

__global__ void finalize_kernel(const int* __restrict__ labels, float* __restrict__ out, int ntok)
{
    __shared__ float red[32];
    int tid = threadIdx.x;
    float local = 0.f;
    for (int t = tid; t < ntok; t += blockDim.x) {
        float hm[4], hs[4], hl = -FLT_MAX;
        #pragma unroll
        for (int s = 0; s < 4; s++) {
            hm[s] = g_pt[0][0][s][t];
            hs[s] = g_pt[0][1][s][t];
            hl = fmaxf(hl, g_pt[0][2][s][t]);
        }
        float loss = lse4(hm, hs) - hl;
        int l = labels[t];
        if (l >= C0LO) {
            int kid = (l < C0HI) ? 1 : 2;
            float tm[4], ts[4], tl = -FLT_MAX;
            #pragma unroll
            for (int s = 0; s < 4; s++) {
                tm[s] = g_pt[kid][0][s][t];
                ts[s] = g_pt[kid][1][s][t];
                tl = fmaxf(tl, g_pt[kid][2][s][t]);
            }
            loss += lse4(tm, ts) - tl;
        }
        if (l == 0) loss = 0.f;
        local += loss;
    }
    #pragma unroll
    for (int o = 16; o > 0; o >>= 1) local += __shfl_xor_sync(0xffffffffu, local, o);
    if ((tid & 31) == 0) red[tid >> 5] = local;
    __syncthreads();
    if (tid < 32) {
        float v = red[tid];
        #pragma unroll
        for (int o = 16; o > 0; o >>= 1) v += __shfl_xor_sync(0xffffffffu, v, o);
        if (tid == 0) out[0] = v / (float)ntok;
    }
}

// ---------------- host launch ----------------
extern "C" void kernel_launch(void* const* d_in, const int* in_sizes, int n_in,
                              void* d_out, int out_size)
{
    const float* inp    = (const float*)d_in[0];
    const int*   labels = (const int*)  d_in[1];
    const float* head_W = (const float*)d_in[2];
    const float* head_b = (const float*)d_in[3];
    const float* t0_pW  = (const float*)d_in[4];
    const float* t0_pb  = (const float*)d_in[5];
    const float* t0_W   = (const float*)d_in[6];
    const float* t0_b   = (const float*)d_in[7];
    const float* t1_pW  = (const float*)d_in[8];
    const float* t1_pb  = (const float*)d_in[9];
    const float* t1_W   = (const float*)d_in[10];
    const float* t1_b   = (const float*)d_in[11];
    const int ntok = in_sizes[1];   // 4096

    cudaFuncSetAttribute(gemm_ce_kernel, cudaFuncAttributeMaxDynamicSharedMemorySize, GEMM_SMEM);

    gather_kernel<<<1, 256>>>(labels, ntok);
    conv_a_kernel<<<(MAXTOK * 128 + 255) / 256, 256>>>(inp);
    conv_w_kernel<<<dim3(HTILES * 2, HKC), 256>>>(head_W, HEADC, HKC, 0);
    conv_w_kernel<<<dim3(T0TILES * 2, T0KC), 256>>>(t0_W, T0C, T0KC, 1);
    conv_w_kernel<<<dim3(T1TILES * 2, T1KC), 256>>>(t1_W, T1C, T1KC, 2);
    proj0_kernel<<<(MAXTOK + 7) / 8, 256>>>(inp, t0_pW, t0_pb);
    proj1_kernel<<<(MAXTOK + 7) / 8, 256>>>(inp, t1_pW, t1_pb);

    gemm_ce_kernel<<<dim3(ntok / 128, 4), 288, GEMM_SMEM>>>(head_b, labels, HEADC, HKC, HTILES, 0, 0);
    gemm_ce_kernel<<<dim3(32, 4), 288, GEMM_SMEM>>>(t0_b, labels, T0C, T0KC, T0TILES, 1, C0LO);
    gemm_ce_kernel<<<dim3(32, 4), 288, GEMM_SMEM>>>(t1_b, labels, T1C, T1KC, T1TILES, 2, C0HI);
    finalize_kernel<<<1, 1024>>>(labels, (float*)d_out, ntok);
}

// round 8
// speedup vs baseline: 11.5747x; 1.4718x over previous
#include <cuda_runtime.h>
#include <cuda_bf16.h>
#include <cfloat>
#include <math.h>
#include <stdint.h>

#define HID    1024
#define HEADC  16002
#define C0LO   16000
#define C0HI   28000
#define P0     256
#define P1     64
#define T0C    12000
#define T1C    8000
#define MAXTOK 4096

#define NTILE   128
#define HTILES  126   // 126*128 = 16128 >= 16002
#define T0TILES 94    // 94*128 = 12032 >= 12000
#define T1TILES 63    // 63*128 = 8064  >= 8000
#define HKC     16    // K chunks of 64 (K=1024)
#define T0KC    4     // K=256
#define T1KC    1     // K=64

#define A_CHUNK 16384   // 128 rows * 128B
#define B_CHUNK 16384   // 128 rows * 128B
#define STAGE   32768
#define NSTAGE  4
#define CMB_OFF   131072  // 3 * 2048 floats = 24576B
#define MB_OFF    155648  // 4 full + 4 empty mbarriers = 64B
#define RLAB_OFF  155712
#define RORIG_OFF 156224
#define GEMM_SMEM 156736

#define SW128(x) ((x) ^ ((((uint32_t)(x)) >> 3) & 0x70u))

// prep dispatch ranges
#define PREP_CONVA   2048
#define PREP_W0      (PREP_CONVA + 252 * HKC)    // 2048 + 4032 = 6080
#define PREP_W1      (PREP_W0 + 188 * T0KC)      // 6080 + 752 = 6832
#define PREP_TOTAL   (PREP_W1 + 126 * T1KC)      // 6832 + 126 = 6958

// ---------------- scratch (static device globals; no allocations) ----------------
__device__ __align__(1024) unsigned char g_Wh[(size_t)HTILES * HKC * B_CHUNK];    // 33 MB
__device__ __align__(1024) unsigned char g_W0[(size_t)T0TILES * T0KC * B_CHUNK];  // 6.2 MB
__device__ __align__(1024) unsigned char g_W1[(size_t)T1TILES * T1KC * B_CHUNK];  // 1.0 MB
__device__ __align__(1024) unsigned char g_Ah[(size_t)32 * HKC * A_CHUNK];        // 8.4 MB
__device__ __align__(1024) unsigned char g_A0[(size_t)32 * T0KC * A_CHUNK];       // 2.1 MB
__device__ __align__(1024) unsigned char g_A1[(size_t)32 * T1KC * A_CHUNK];       // 0.5 MB
__device__ int   g_idx0[MAXTOK];
__device__ int   g_idx1[MAXTOK];
__device__ int   g_cnt[2];
__device__ float g_pt[3][3][4][MAXTOK];  // [kernel][m/s/lab][split][token]

// ---------------- PTX helpers (baseline PTX only; no 'a'-target features) ----------------
__device__ __forceinline__ uint32_t smem_u32(const void* p) {
    uint32_t a;
    asm("{ .reg .u64 t; cvta.to.shared.u64 t, %1; cvt.u32.u64 %0, t; }" : "=r"(a) : "l"(p));
    return a;
}
#define MBARRIER_INIT(addr, cnt) \
    asm volatile("mbarrier.init.shared.b64 [%0], %1;" :: "r"((uint32_t)(addr)), "r"((uint32_t)(cnt)) : "memory")
#define MBARRIER_EXPECT_TX(addr, tx) \
    asm volatile("mbarrier.arrive.expect_tx.shared.b64 _, [%0], %1;" :: "r"((uint32_t)(addr)), "r"((uint32_t)(tx)) : "memory")
#define MBARRIER_ARRIVE(addr) \
    asm volatile("mbarrier.arrive.shared.b64 _, [%0];" :: "r"((uint32_t)(addr)) : "memory")
#define MBARRIER_WAIT(addr, par) do { \
    uint32_t _m = (uint32_t)(addr); uint32_t _p = (uint32_t)(par); uint32_t _d; \
    asm volatile("{\n\t.reg .pred p;\n\t" \
        "mbarrier.try_wait.parity.acquire.cta.shared::cta.b64 p, [%1], %2;\n\t" \
        "selp.b32 %0, 1, 0, p;\n\t}" : "=r"(_d) : "r"(_m), "r"(_p) : "memory"); \
    if (!_d) { \
        asm volatile("{\n\t.reg .pred P1;\n\t" \
            "WL_%=:\n\t" \
            "mbarrier.try_wait.parity.acquire.cta.shared::cta.b64 P1, [%0], %1, 0x989680;\n\t" \
            "@P1 bra.uni WD_%=;\n\t" \
            "bra.uni WL_%=;\n\t" \
            "WD_%=:\n\t}" :: "r"(_m), "r"(_p) : "memory"); \
    } } while (0)

__device__ __forceinline__ void bulk_g2s(uint32_t dst, const void* src, uint32_t bytes, uint32_t mbar) {
    asm volatile("cp.async.bulk.shared::cluster.global.mbarrier::complete_tx::bytes [%0], [%1], %2, [%3];"
        :: "r"(dst), "l"(src), "r"(bytes), "r"(mbar) : "memory");
}
__device__ __forceinline__ void ldsm4(uint32_t* r, uint32_t addr) {
    asm volatile("ldmatrix.sync.aligned.m8n8.x4.shared.b16 {%0,%1,%2,%3}, [%4];"
        : "=r"(r[0]), "=r"(r[1]), "=r"(r[2]), "=r"(r[3]) : "r"(addr));
}
__device__ __forceinline__ void mma16816(float* d, const uint32_t* a, const uint32_t* b) {
    asm volatile("mma.sync.aligned.m16n8k16.row.col.f32.bf16.bf16.f32 "
        "{%0,%1,%2,%3}, {%4,%5,%6,%7}, {%8,%9}, {%0,%1,%2,%3};"
        : "+f"(d[0]), "+f"(d[1]), "+f"(d[2]), "+f"(d[3])
        : "r"(a[0]), "r"(a[1]), "r"(a[2]), "r"(a[3]), "r"(b[0]), "r"(b[1]));
}
__device__ __forceinline__ uint32_t pack_bf2(float a, float b) {
    __nv_bfloat162 h = __floats2bfloat162_rn(a, b);
    return *reinterpret_cast<uint32_t*>(&h);
}

// ---------------- gather tokens per cluster ----------------
__global__ void gather_kernel(const int* __restrict__ labels, int ntok)
{
    __shared__ int c0, c1;
    if (threadIdx.x == 0) { c0 = 0; c1 = 0; }
    __syncthreads();
    for (int i = threadIdx.x; i < ntok; i += blockDim.x) {
        int l = labels[i];
        if (l >= C0LO) {
            if (l < C0HI) g_idx0[atomicAdd(&c0, 1)] = i;
            else          g_idx1[atomicAdd(&c1, 1)] = i;
        }
    }
    __syncthreads();
    if (threadIdx.x == 0) { g_cnt[0] = c0; g_cnt[1] = c1; }
}

// ---------------- merged prep: conv_a + conv_w (head, t0, t1) ----------------
__global__ void prep_kernel(const float* __restrict__ inp,
                            const float* __restrict__ head_W,
                            const float* __restrict__ t0_W,
                            const float* __restrict__ t1_W)
{
    __shared__ float ws[64][65];
    const int b = blockIdx.x, tid = threadIdx.x;

    if (b < PREP_CONVA) {
        // ---- conv_a: inp -> bf16 swizzled tiled A (head) ----
        int idx = b * 256 + tid;   // one 16B unit
        int token = idx >> 7;
        int unit  = idx & 127;
        int kc = unit >> 3, u = unit & 7;
        const float4* src = reinterpret_cast<const float4*>(inp + (size_t)token * HID + kc * 64 + u * 8);
        float4 v0 = src[0], v1 = src[1];
        uint4 o;
        o.x = pack_bf2(v0.x, v0.y); o.y = pack_bf2(v0.z, v0.w);
        o.z = pack_bf2(v1.x, v1.y); o.w = pack_bf2(v1.z, v1.w);
        int r = token & 127;
        size_t off = ((size_t)(token >> 7) * HKC + kc) * A_CHUNK
                   + (r >> 3) * 1024 + SW128((r & 7) * 128 + u * 16);
        *reinterpret_cast<uint4*>(g_Ah + off) = o;
        return;
    }

    // ---- conv_w: W [K][C] row-major -> bf16 swizzled tiled B ----
    const float* W; unsigned char* out; int C, kchunks, nct, r;
    if (b < PREP_W0)      { W = head_W; out = g_Wh; C = HEADC; kchunks = HKC;  nct = 252; r = b - PREP_CONVA; }
    else if (b < PREP_W1) { W = t0_W;   out = g_W0; C = T0C;   kchunks = T0KC; nct = 188; r = b - PREP_W0; }
    else                  { W = t1_W;   out = g_W1; C = T1C;   kchunks = T1KC; nct = 126; r = b - PREP_W1; }
    const int ct = r % nct;   // 64-class group
    const int kt = r / nct;   // 64-k group == kc

    for (int e = tid; e < 64 * 64; e += 256) {
        int kr = e >> 6, cc = e & 63;
        int c = ct * 64 + cc;
        ws[kr][cc] = (c < C) ? W[(size_t)(kt * 64 + kr) * C + c] : 0.f;
    }
    __syncthreads();
    for (int e = tid; e < 512; e += 256) {
        int n64 = e >> 3, u = e & 7;
        int ng = ct * 64 + n64;
        int tile = ng >> 7, nt = ng & 127;
        uint4 o;
        o.x = pack_bf2(ws[u * 8 + 0][n64], ws[u * 8 + 1][n64]);
        o.y = pack_bf2(ws[u * 8 + 2][n64], ws[u * 8 + 3][n64]);
        o.z = pack_bf2(ws[u * 8 + 4][n64], ws[u * 8 + 5][n64]);
        o.w = pack_bf2(ws[u * 8 + 6][n64], ws[u * 8 + 7][n64]);
        size_t off = ((size_t)(tile * kchunks + kt)) * B_CHUNK
                   + (nt >> 3) * 1024 + SW128((nt & 7) * 128 + u * 16);
        *reinterpret_cast<uint4*>(out + off) = o;
    }
}

// ---------------- merged projections -> bf16 swizzled tiled A for tails ----------------
__global__ void projs_kernel(const float* __restrict__ inp,
                             const float* __restrict__ t0_pW, const float* __restrict__ t0_pb,
                             const float* __restrict__ t1_pW, const float* __restrict__ t1_pb)
{
    __shared__ float As[8][HID];
    const int tid = threadIdx.x;

    if (blockIdx.x < 512) {
        // ---- proj0 ----
        int n = g_cnt[0];
        int g0 = blockIdx.x * 8;
        if (g0 >= n) return;
        for (int e = tid; e < 8 * HID; e += 256) {
            int r = e >> 10, k = e & 1023;
            int g = g0 + r;
            As[r][k] = (g < n) ? inp[(size_t)g_idx0[g] * HID + k] : 0.f;
        }
        __syncthreads();
        float acc[8];
        #pragma unroll
        for (int t = 0; t < 8; t++) acc[t] = 0.f;
        float bj = t0_pb[tid];
        #pragma unroll 4
        for (int k = 0; k < HID; k++) {
            float w = t0_pW[k * P0 + tid];
            #pragma unroll
            for (int t = 0; t < 8; t++) acc[t] = fmaf(As[t][k], w, acc[t]);
        }
        int kc = tid >> 6, kk = tid & 63;
        #pragma unroll
        for (int t = 0; t < 8; t++) {
            int g = g0 + t;
            if (g < n) {
                int r = g & 127;
                size_t off = ((size_t)(g >> 7) * T0KC + kc) * A_CHUNK
                           + (r >> 3) * 1024 + SW128((r & 7) * 128 + kk * 2);
                *reinterpret_cast<__nv_bfloat16*>(g_A0 + off) = __float2bfloat16(acc[t] + bj);
            }
        }
    } else {
        // ---- proj1 ----
        int n = g_cnt[1];
        int g0 = (blockIdx.x - 512) * 8;
        if (g0 >= n) return;
        for (int e = tid; e < 8 * HID; e += 256) {
            int r = e >> 10, k = e & 1023;
            int g = g0 + r;
            As[r][k] = (g < n) ? inp[(size_t)g_idx1[g] * HID + k] : 0.f;
        }
        __syncthreads();
        int j  = tid & 63;
        int tg = tid >> 6;
        float acc0 = 0.f, acc1 = 0.f;
        float bj = t1_pb[j];
        #pragma unroll 4
        for (int k = 0; k < HID; k++) {
            float w = t1_pW[k * P1 + j];
            acc0 = fmaf(As[tg * 2 + 0][k], w, acc0);
            acc1 = fmaf(As[tg * 2 + 1][k], w, acc1);
        }
        #pragma unroll
        for (int t = 0; t < 2; t++) {
            int g = g0 + tg * 2 + t;
            if (g < n) {
                int r = g & 127;
                float v = (t == 0) ? acc0 : acc1;
                size_t off = ((size_t)(g >> 7)) * A_CHUNK
                           + (r >> 3) * 1024 + SW128((r & 7) * 128 + j * 2);
                *reinterpret_cast<__nv_bfloat16*>(g_A1 + off) = __float2bfloat16(v + bj);
            }
        }
    }
}

// ---------------- merged fused mma.sync GEMM + online logsumexp ----------------
// grid (4 splits, 96): y<32 head, y<64 tail0, else tail1. 8 MMA warps + producer warp.
__global__ void __launch_bounds__(288, 1)
gemm_ce_all(const float* __restrict__ head_b, const float* __restrict__ t0_b,
            const float* __restrict__ t1_b, const int* __restrict__ labels)
{
    const int split = blockIdx.x, my = blockIdx.y;
    int kid, mblock;
    const float* bias;
    const unsigned char *Asw, *Bsw;
    int C, kchunks, tiles_total, lo;
    if (my < 32)      { kid = 0; mblock = my;      bias = head_b; Asw = g_Ah; Bsw = g_Wh; C = HEADC; kchunks = HKC;  tiles_total = HTILES;  lo = 0; }
    else if (my < 64) { kid = 1; mblock = my - 32; bias = t0_b;   Asw = g_A0; Bsw = g_W0; C = T0C;   kchunks = T0KC; tiles_total = T0TILES; lo = C0LO; }
    else              { kid = 2; mblock = my - 64; bias = t1_b;   Asw = g_A1; Bsw = g_W1; C = T1C;   kchunks = T1KC; tiles_total = T1TILES; lo = C0HI; }
    if (kid != 0 && mblock * 128 >= g_cnt[kid - 1]) return;

    extern __shared__ unsigned char sm[];
    uint32_t sb = smem_u32(sm);
    const int tid = threadIdx.x, wid = tid >> 5, lane = tid & 31;

    // split tile range
    const int q4 = tiles_total >> 2, rem = tiles_total & 3;
    const int tbeg = split * q4 + min(split, rem);
    const int tcnt = q4 + (split < rem ? 1 : 0);
    const int total = tcnt * kchunks;

    int* rlabs = reinterpret_cast<int*>(sm + RLAB_OFF);
    int* rorig = reinterpret_cast<int*>(sm + RORIG_OFF);

    if (tid == 0) {
        #pragma unroll
        for (int s = 0; s < NSTAGE; s++) {
            MBARRIER_INIT(sb + MB_OFF + s * 8, 1);         // full[s]
            MBARRIER_INIT(sb + MB_OFF + 32 + s * 8, 256);  // empty[s]
        }
    }
    if (tid < 128) {
        if (kid == 0) {
            int orig = mblock * 128 + tid;
            int l = labels[orig];
            rlabs[tid] = (l < C0LO) ? l : ((l < C0HI) ? C0LO : C0LO + 1);
            rorig[tid] = orig;
        } else {
            int n = g_cnt[kid - 1];
            int g = mblock * 128 + tid;
            if (g < n) {
                int o = ((kid == 1) ? g_idx0 : g_idx1)[g];
                rorig[tid] = o; rlabs[tid] = labels[o] - lo;
            } else { rorig[tid] = -1; rlabs[tid] = -2; }
        }
    }
    __syncthreads();

    if (wid == 8) {
        // ---------------- dedicated producer ----------------
        if (lane == 0) {
            #pragma unroll 1
            for (int cc = 0; cc < total; cc++) {
                int st = cc & (NSTAGE - 1), ph = cc >> 2;
                uint32_t fb = sb + MB_OFF + st * 8;
                uint32_t eb = sb + MB_OFF + 32 + st * 8;
                if (cc >= NSTAGE) MBARRIER_WAIT(eb, (ph - 1) & 1);
                MBARRIER_EXPECT_TX(fb, A_CHUNK + B_CHUNK);
                int tile = tbeg + cc / kchunks, kc = cc % kchunks;
                bulk_g2s(sb + st * STAGE, Asw + ((size_t)mblock * kchunks + kc) * A_CHUNK, A_CHUNK, fb);
                bulk_g2s(sb + st * STAGE + A_CHUNK, Bsw + ((size_t)tile * kchunks + kc) * B_CHUNK, B_CHUNK, fb);
            }
        }
    } else {
        // ---------------- MMA consumers ----------------
        const int wm = wid >> 2, wn = wid & 3;
        const int tq = lane >> 2, tc = lane & 3;

        const int sub = lane >> 3, li = lane & 7;
        const uint32_t vx = (uint32_t)li << 4;
        uint32_t aoff[4], boff[2];
        {
            int arowadd = (sub & 1) * 8;
            #pragma unroll
            for (int mt = 0; mt < 4; mt++) {
                int row = wm * 64 + mt * 16 + arowadd + li;
                aoff[mt] = ((uint32_t)(row >> 3) << 10) + ((uint32_t)li << 7);
            }
            int browadd = (sub >> 1) * 8;
            #pragma unroll
            for (int nb = 0; nb < 2; nb++) {
                int row = wn * 32 + nb * 16 + browadd + li;
                boff[nb] = ((uint32_t)(row >> 3) << 10) + ((uint32_t)li << 7);
            }
        }
        const uint32_t auo = (uint32_t)(sub >> 1) << 4;
        const uint32_t buo = (uint32_t)(sub & 1) << 4;

        float rm[4][2], rs[4][2], rl[4][2];
        int rlb[4][2];
        #pragma unroll
        for (int mt = 0; mt < 4; mt++)
            #pragma unroll
            for (int h = 0; h < 2; h++) {
                rm[mt][h] = -FLT_MAX; rs[mt][h] = 0.f; rl[mt][h] = -FLT_MAX;
                rlb[mt][h] = rlabs[wm * 64 + mt * 16 + tq + h * 8];
            }

        int cc = 0;
        #pragma unroll 1
        for (int tt = 0; tt < tcnt; tt++) {
            float acc[4][4][4];
            #pragma unroll
            for (int mt = 0; mt < 4; mt++)
                #pragma unroll
                for (int nt = 0; nt < 4; nt++)
                    #pragma unroll
                    for (int e = 0; e < 4; e++) acc[mt][nt][e] = 0.f;

            #pragma unroll 1
            for (int kc = 0; kc < kchunks; kc++, cc++) {
                const int st = cc & (NSTAGE - 1), ph = cc >> 2;
                const uint32_t fb = sb + MB_OFF + st * 8;
                const uint32_t eb = sb + MB_OFF + 32 + st * 8;
                MBARRIER_WAIT(fb, ph & 1);
                const uint32_t Ab = sb + st * STAGE;
                const uint32_t Bb = Ab + A_CHUNK;
                #pragma unroll
                for (int ks = 0; ks < 4; ks++) {
                    const uint32_t kx = (uint32_t)ks << 5;
                    uint32_t a[4][4], bfr[4][2];
                    #pragma unroll
                    for (int mt = 0; mt < 4; mt++)
                        ldsm4(a[mt], Ab + aoff[mt] + ((kx + auo) ^ vx));
                    #pragma unroll
                    for (int nb = 0; nb < 2; nb++) {
                        uint32_t t4[4];
                        ldsm4(t4, Bb + boff[nb] + ((kx + buo) ^ vx));
                        bfr[nb * 2 + 0][0] = t4[0]; bfr[nb * 2 + 0][1] = t4[1];
                        bfr[nb * 2 + 1][0] = t4[2]; bfr[nb * 2 + 1][1] = t4[3];
                    }
                    #pragma unroll
                    for (int mt = 0; mt < 4; mt++)
                        #pragma unroll
                        for (int nt = 0; nt < 4; nt++)
                            mma16816(acc[mt][nt], a[mt], bfr[nt]);
                }
                MBARRIER_ARRIVE(eb);
            }
            // ---- epilogue for this tile (online logsumexp, register-resident) ----
            const int cb0 = (tbeg + tt) * NTILE + wn * 32 + tc * 2;
            #pragma unroll
            for (int mt = 0; mt < 4; mt++)
                #pragma unroll
                for (int h = 0; h < 2; h++) {
                    float v[8];
                    float tmax = -FLT_MAX;
                    #pragma unroll
                    for (int nt = 0; nt < 4; nt++)
                        #pragma unroll
                        for (int e = 0; e < 2; e++) {
                            int c = cb0 + nt * 8 + e;
                            float x = -FLT_MAX;
                            if (c < C) x = acc[mt][nt][h * 2 + e] + __ldg(bias + c);
                            v[nt * 2 + e] = x;
                            tmax = fmaxf(tmax, x);
                            if (c == rlb[mt][h]) rl[mt][h] = x;
                        }
                    float nm = fmaxf(rm[mt][h], tmax);
                    if (nm > -1e37f) {
                        float ssum = rs[mt][h] * __expf(rm[mt][h] - nm);
                        #pragma unroll
                        for (int qq = 0; qq < 8; qq++) ssum += __expf(v[qq] - nm);
                        rs[mt][h] = ssum; rm[mt][h] = nm;
                    }
                }
        }

        // ---- stash partials (16 per row) ----
        float* cm = reinterpret_cast<float*>(sm + CMB_OFF);
        float* cs = cm + 2048;
        float* cl = cm + 4096;
        #pragma unroll
        for (int mt = 0; mt < 4; mt++)
            #pragma unroll
            for (int h = 0; h < 2; h++) {
                int r = wm * 64 + mt * 16 + tq + h * 8;
                int p = wn * 4 + tc;
                cm[r * 16 + p] = rm[mt][h];
                cs[r * 16 + p] = rs[mt][h];
                cl[r * 16 + p] = rl[mt][h];
            }
    }
    __syncthreads();
    if (tid < 128) {
        float* cm = reinterpret_cast<float*>(sm + CMB_OFF);
        float* cs = cm + 2048;
        float* cl = cm + 4096;
        int r = tid;
        float M = -FLT_MAX, L = -FLT_MAX;
        #pragma unroll 4
        for (int p = 0; p < 16; p++) {
            M = fmaxf(M, cm[r * 16 + p]);
            L = fmaxf(L, cl[r * 16 + p]);
        }
        float S = 0.f;
        #pragma unroll 4
        for (int p = 0; p < 16; p++) {
            float mm = cm[r * 16 + p];
            if (mm > -1e37f) S += cs[r * 16 + p] * __expf(mm - M);
        }
        int orig = rorig[r];
        if (orig >= 0) {
            g_pt[kid][0][split][orig] = M;
            g_pt[kid][1][split][orig] = S;
            g_pt[kid][2][split][orig] = L;
        }
    }
}

// ---------------- finalize: combine splits, mask, mean ----------------
__device__ __forceinline__ float lse4(const float* mm, const float* ss) {
    float M = fmaxf(fmaxf(mm[0], mm[1]), fmaxf(mm[2], mm[3]));
    float S = ss[0] * __expf(mm[0] - M) + ss[1] * __expf(mm[1] - M)
            + ss[2] * __expf(mm[2] - M) + ss[3] * __expf(mm[3] - M);
    return M + logf(S);
}

__global__ void finalize_kernel(const int* __restrict__ labels, float* __restrict__ out, int ntok)
{
    __shared__ float red[32];
    int tid = threadIdx.x;
    float local = 0.f;
    for (int t = tid; t < ntok; t += blockDim.x) {
        float hm[4], hs[4], hl = -FLT_MAX;
        #pragma unroll
        for (int s = 0; s < 4; s++) {
            hm[s] = g_pt[0][0][s][t];
            hs[s] = g_pt[0][1][s][t];
            hl = fmaxf(hl, g_pt[0][2][s][t]);
        }
        float loss = lse4(hm, hs) - hl;
        int l = labels[t];
        if (l >= C0LO) {
            int kid = (l < C0HI) ? 1 : 2;
            float tm[4], ts[4], tl = -FLT_MAX;
            #pragma unroll
            for (int s = 0; s < 4; s++) {
                tm[s] = g_pt[kid][0][s][t];
                ts[s] = g_pt[kid][1][s][t];
                tl = fmaxf(tl, g_pt[kid][2][s][t]);
            }
            loss += lse4(tm, ts) - tl;
        }
        if (l == 0) loss = 0.f;
        local += loss;
    }
    #pragma unroll
    for (int o = 16; o > 0; o >>= 1) local += __shfl_xor_sync(0xffffffffu, local, o);
    if ((tid & 31) == 0) red[tid >> 5] = local;
    __syncthreads();
    if (tid < 32) {
        float v = red[tid];
        #pragma unroll
        for (int o = 16; o > 0; o >>= 1) v += __shfl_xor_sync(0xffffffffu, v, o);
        if (tid == 0) out[0] = v / (float)ntok;
    }
}

// ---------------- host launch ----------------
extern "C" void kernel_launch(void* const* d_in, const int* in_sizes, int n_in,
                              void* d_out, int out_size)
{
    const float* inp    = (const float*)d_in[0];
    const int*   labels = (const int*)  d_in[1];
    const float* head_W = (const float*)d_in[2];
    const float* head_b = (const float*)d_in[3];
    const float* t0_pW  = (const float*)d_in[4];
    const float* t0_pb  = (const float*)d_in[5];
    const float* t0_W   = (const float*)d_in[6];
    const float* t0_b   = (const float*)d_in[7];
    const float* t1_pW  = (const float*)d_in[8];
    const float* t1_pb  = (const float*)d_in[9];
    const float* t1_W   = (const float*)d_in[10];
    const float* t1_b   = (const float*)d_in[11];
    const int ntok = in_sizes[1];   // 4096

    cudaFuncSetAttribute(gemm_ce_all, cudaFuncAttributeMaxDynamicSharedMemorySize, GEMM_SMEM);

    // launch 0: all weight/input conversions (independent blocks)
    prep_kernel<<<PREP_TOTAL, 256>>>(inp, head_W, t0_W, t1_W);
    // launch 1: token gather per cluster
    gather_kernel<<<1, 256>>>(labels, ntok);
    // launch 2: tail projections (need gather)
    projs_kernel<<<1024, 256>>>(inp, t0_pW, t0_pb, t1_pW, t1_pb);
    // launch 3: all GEMM+CE work in one grid (profiled slot)
    gemm_ce_all<<<dim3(4, 96), 288, GEMM_SMEM>>>(head_b, t0_b, t1_b, labels);
    // launch 4: reduce
    finalize_kernel<<<1, 1024>>>(labels, (float*)d_out, ntok);
}